// round 2
// baseline (speedup 1.0000x reference)
#include <cuda_runtime.h>
#include <math.h>

#define B_    8
#define N_    2048
#define DIN   256
#define DOUT  128
#define ROWZ  75          // rows [0,75) get attscore = 0

#define TM    64
#define TN    64
#define QKS   68          // padded stride for transposed Q/K tiles (16B-aligned, conflict-mitigating)

// Scratch (device globals: allocation-free)
__device__ float g_Wh [B_ * N_ * DOUT];   // 8 MB
__device__ float g_Whn[B_ * N_ * DOUT];   // 8 MB

// ---------------------------------------------------------------------------
// Phase 1: Wh = h @ W   (M = B*N = 16384, K = 256, N = 128)
// BM=64, BK=32, 256 threads, 4x8 micro-tile per thread.
// ---------------------------------------------------------------------------
__global__ __launch_bounds__(256) void gemm_hW(const float* __restrict__ h,
                                               const float* __restrict__ W) {
    __shared__ float hs[32 * QKS];   // [k][row], stride 68
    __shared__ float Ws[32 * 128];   // [k][d]

    const int r0  = blockIdx.x * 64;
    const int tid = threadIdx.x;
    const int tx  = tid & 15;        // d-group: cols tx*8 .. tx*8+7
    const int ty  = tid >> 4;        // row-group: rows ty*4 .. ty*4+3

    float acc[4][8];
#pragma unroll
    for (int i = 0; i < 4; i++)
#pragma unroll
        for (int j = 0; j < 8; j++) acc[i][j] = 0.0f;

    for (int k0 = 0; k0 < DIN; k0 += 32) {
        __syncthreads();
        // load h tile (64 rows x 32 k), transposed into hs[k][row]
#pragma unroll
        for (int i = tid; i < 64 * 32; i += 256) {
            int row = i >> 5, kk = i & 31;
            hs[kk * QKS + row] = h[(size_t)(r0 + row) * DIN + k0 + kk];
        }
        // load W tile (32 k x 128 d)
#pragma unroll
        for (int i = tid; i < 32 * 128; i += 256) {
            int kk = i >> 7, d = i & 127;
            Ws[kk * 128 + d] = W[(size_t)(k0 + kk) * DOUT + d];
        }
        __syncthreads();

#pragma unroll 8
        for (int kk = 0; kk < 32; kk++) {
            float4 hv = *(const float4*)&hs[kk * QKS + ty * 4];
            float4 w0 = *(const float4*)&Ws[kk * 128 + tx * 8];
            float4 w1 = *(const float4*)&Ws[kk * 128 + tx * 8 + 4];
            float hr[4] = {hv.x, hv.y, hv.z, hv.w};
            float wr[8] = {w0.x, w0.y, w0.z, w0.w, w1.x, w1.y, w1.z, w1.w};
#pragma unroll
            for (int i = 0; i < 4; i++)
#pragma unroll
                for (int j = 0; j < 8; j++) acc[i][j] += hr[i] * wr[j];
        }
    }

#pragma unroll
    for (int i = 0; i < 4; i++) {
        float* dst = g_Wh + (size_t)(r0 + ty * 4 + i) * DOUT + tx * 8;
        *(float4*)dst       = make_float4(acc[i][0], acc[i][1], acc[i][2], acc[i][3]);
        *(float4*)(dst + 4) = make_float4(acc[i][4], acc[i][5], acc[i][6], acc[i][7]);
    }
}

// ---------------------------------------------------------------------------
// Phase 1b: row L2 norms -> g_Whn  (one warp per row)
// ---------------------------------------------------------------------------
__global__ __launch_bounds__(256) void normalize_rows() {
    const int row  = blockIdx.x * 8 + (threadIdx.x >> 5);
    const int lane = threadIdx.x & 31;
    float4 a = ((const float4*)(g_Wh + (size_t)row * DOUT))[lane];
    float ss = a.x * a.x + a.y * a.y + a.z * a.z + a.w * a.w;
#pragma unroll
    for (int o = 16; o >= 1; o >>= 1) ss += __shfl_xor_sync(0xffffffffu, ss, o);
    float inv = 1.0f / fmaxf(sqrtf(ss), 1e-12f);
    ((float4*)(g_Whn + (size_t)row * DOUT))[lane] =
        make_float4(a.x * inv, a.y * inv, a.z * inv, a.w * inv);
}

// ---------------------------------------------------------------------------
// Phase 2: fused masked-softmax attention.
//   s = Whn_q . Whn_m  (0 if global q-row < 75)
//   p = adj_eye ? exp(s) : 0 ;  out = elu( (sum_m p*Wh_m) / sum_m p )
// Tile: 64 queries x 64 keys, D = 128, 256 threads, 1 block per (b, q-tile).
// ---------------------------------------------------------------------------
__global__ __launch_bounds__(256) void attn(const int* __restrict__ adj,
                                            float* __restrict__ out) {
    extern __shared__ float sm[];
    float* Qs = sm;                       // [128][QKS]  Whn^T of query tile
    float* Ks = Qs + 128 * QKS;           // [128][QKS]  Whn^T of key tile
    float* Vs = Ks + 128 * QKS;           // [64][128]   Wh key tile (natural)
    float* Ps = Vs + 64 * 128;            // [64 q][64 m]
    float* dn = Ps + 64 * 64;             // [64] softmax denominators

    const int b   = blockIdx.y;
    const int q0  = blockIdx.x * TM;
    const int tid = threadIdx.x;
    const int tx  = tid & 15;
    const int ty  = tid >> 4;

    const float* WhnB = g_Whn + (size_t)b * N_ * DOUT;
    const float* WhB  = g_Wh  + (size_t)b * N_ * DOUT;
    const int*   adjB = adj   + (size_t)b * N_ * N_;

    // Q tile, transposed
#pragma unroll
    for (int i = tid; i < TM * DOUT; i += 256) {
        int q = i >> 7, d = i & 127;
        Qs[d * QKS + q] = WhnB[(size_t)(q0 + q) * DOUT + d];
    }
    if (tid < TM) dn[tid] = 0.0f;

    float acc[4][8];
#pragma unroll
    for (int i = 0; i < 4; i++)
#pragma unroll
        for (int j = 0; j < 8; j++) acc[i][j] = 0.0f;

    for (int m0 = 0; m0 < N_; m0 += TN) {
        __syncthreads();   // previous P*V readers done before overwriting tiles
        // K tile (Whn), transposed
#pragma unroll
        for (int i = tid; i < TN * DOUT; i += 256) {
            int m = i >> 7, d = i & 127;
            Ks[d * QKS + m] = WhnB[(size_t)(m0 + m) * DOUT + d];
        }
        // V tile (Wh), natural, vectorized copy
        {
            const float4* vsrc = (const float4*)(WhB + (size_t)m0 * DOUT);
#pragma unroll
            for (int i = tid; i < TN * DOUT / 4; i += 256)
                ((float4*)Vs)[i] = vsrc[i];
        }
        // prefetch adjacency for this thread's 4x4 S fragment
        int4 am[4];
#pragma unroll
        for (int i = 0; i < 4; i++)
            am[i] = *(const int4*)(adjB + (size_t)(q0 + ty * 4 + i) * N_ + m0 + tx * 4);
        __syncthreads();

        // S = Q . K^T  (4x4 micro-tile)
        float s[4][4];
#pragma unroll
        for (int i = 0; i < 4; i++)
#pragma unroll
            for (int j = 0; j < 4; j++) s[i][j] = 0.0f;

#pragma unroll 8
        for (int k = 0; k < DOUT; k++) {
            float4 qv = *(const float4*)&Qs[k * QKS + ty * 4];
            float4 kv = *(const float4*)&Ks[k * QKS + tx * 4];
            float qr[4] = {qv.x, qv.y, qv.z, qv.w};
            float kr[4] = {kv.x, kv.y, kv.z, kv.w};
#pragma unroll
            for (int i = 0; i < 4; i++)
#pragma unroll
                for (int j = 0; j < 4; j++) s[i][j] += qr[i] * kr[j];
        }

        // mask + exp + row-sum, stage P into smem
#pragma unroll
        for (int i = 0; i < 4; i++) {
            const bool zrow = (q0 + ty * 4 + i) < ROWZ;
            const int* ai = &am[i].x;
            float rs = 0.0f;
#pragma unroll
            for (int j = 0; j < 4; j++) {
                float sv = zrow ? 0.0f : s[i][j];
                float pv = (ai[j] > 0) ? __expf(sv) : 0.0f;
                s[i][j] = pv;
                rs += pv;
            }
            rs += __shfl_xor_sync(0xffffffffu, rs, 1);
            rs += __shfl_xor_sync(0xffffffffu, rs, 2);
            rs += __shfl_xor_sync(0xffffffffu, rs, 4);
            rs += __shfl_xor_sync(0xffffffffu, rs, 8);
            if (tx == 0) dn[ty * 4 + i] += rs;   // single writer per row, per tile
            *(float4*)&Ps[(ty * 4 + i) * 64 + tx * 4] =
                make_float4(s[i][0], s[i][1], s[i][2], s[i][3]);
        }
        __syncthreads();

        // acc += P (64x64) . V (64x128), 4x8 micro-tile
#pragma unroll 4
        for (int m = 0; m < TN; m++) {
            float4 v0 = *(const float4*)&Vs[m * DOUT + tx * 8];
            float4 v1 = *(const float4*)&Vs[m * DOUT + tx * 8 + 4];
#pragma unroll
            for (int i = 0; i < 4; i++) {
                float pa = Ps[(ty * 4 + i) * 64 + m];   // broadcast across tx lanes
                acc[i][0] += pa * v0.x;  acc[i][1] += pa * v0.y;
                acc[i][2] += pa * v0.z;  acc[i][3] += pa * v0.w;
                acc[i][4] += pa * v1.x;  acc[i][5] += pa * v1.y;
                acc[i][6] += pa * v1.z;  acc[i][7] += pa * v1.w;
            }
        }
    }

    // epilogue: divide by denominator, ELU, store
#pragma unroll
    for (int i = 0; i < 4; i++) {
        float d   = dn[ty * 4 + i];
        float inv = 1.0f / fmaxf(d, 1e-30f);
        float o[8];
#pragma unroll
        for (int j = 0; j < 8; j++) {
            float v = acc[i][j] * inv;
            o[j] = (v > 0.0f) ? v : expm1f(v);
        }
        float* dst = out + ((size_t)b * N_ + q0 + ty * 4 + i) * DOUT + tx * 8;
        *(float4*)dst       = make_float4(o[0], o[1], o[2], o[3]);
        *(float4*)(dst + 4) = make_float4(o[4], o[5], o[6], o[7]);
    }
}

// ---------------------------------------------------------------------------
// Launch
// ---------------------------------------------------------------------------
extern "C" void kernel_launch(void* const* d_in, const int* in_sizes, int n_in,
                              void* d_out, int out_size) {
    const float* h       = (const float*)d_in[0];   // [8,2048,256] f32
    // d_in[1] = adj (unused by the reference math)
    const int*   adj_eye = (const int*)d_in[2];     // [8,2048,2048] i32
    const float* W       = (const float*)d_in[3];   // [256,128] f32
    float* out = (float*)d_out;                     // [8,2048,128] f32

    const int smem_bytes = (128 * QKS + 128 * QKS + 64 * 128 + 64 * 64 + 64) * 4;
    cudaFuncSetAttribute(attn, cudaFuncAttributeMaxDynamicSharedMemorySize, smem_bytes);

    gemm_hW<<<(B_ * N_) / 64, 256>>>(h, W);
    normalize_rows<<<(B_ * N_) / 8, 256>>>();
    attn<<<dim3(N_ / TM, B_), 256, smem_bytes>>>(adj_eye, out);
}

// round 3
// speedup vs baseline: 3.0477x; 3.0477x over previous
#include <cuda_runtime.h>
#include <math.h>

#define B_   8
#define N_   2048
#define DIN  256
#define DOUT 128
#define ROWZ 75        // rows [0,75) get attscore = 0
#define TM   128       // queries per block
#define TN   128       // keys per tile
#define ST   132       // smem row stride in floats (pad 4 -> conflict-free frag loads)

// Scratch (device globals: allocation-free). Values stored pre-rounded to tf32.
__device__ float g_Wh [B_ * N_ * DOUT];   // 8 MB
__device__ float g_Whn[B_ * N_ * DOUT];   // 8 MB

__device__ __forceinline__ float to_tf32(float x) {
    unsigned u;
    asm("cvt.rna.tf32.f32 %0, %1;" : "=r"(u) : "f"(x));
    return __uint_as_float(u);
}

__device__ __forceinline__ void mma_tf32(float d[4], const unsigned a[4], const unsigned b[2]) {
    asm volatile(
        "mma.sync.aligned.m16n8k8.row.col.f32.tf32.tf32.f32 "
        "{%0,%1,%2,%3}, {%4,%5,%6,%7}, {%8,%9}, {%0,%1,%2,%3};\n"
        : "+f"(d[0]), "+f"(d[1]), "+f"(d[2]), "+f"(d[3])
        : "r"(a[0]), "r"(a[1]), "r"(a[2]), "r"(a[3]), "r"(b[0]), "r"(b[1]));
}

// ---------------------------------------------------------------------------
// Phase 1: Wh = h @ W, fused row-L2-norm. Writes g_Wh (tf32-rounded) and
// g_Whn = tf32(Wh / max(||Wh||, 1e-12)).
// BM=64, BK=32, 256 threads, 4x8 micro-tile per thread.
// ---------------------------------------------------------------------------
__global__ __launch_bounds__(256) void gemm_hW(const float* __restrict__ h,
                                               const float* __restrict__ W) {
    __shared__ float hs[32 * 68];    // [k][row], stride 68
    __shared__ float Ws[32 * 128];   // [k][d]

    const int r0  = blockIdx.x * 64;
    const int tid = threadIdx.x;
    const int tx  = tid & 15;        // d-group: cols tx*8 .. tx*8+7
    const int ty  = tid >> 4;        // row-group: rows ty*4 .. ty*4+3

    float acc[4][8];
#pragma unroll
    for (int i = 0; i < 4; i++)
#pragma unroll
        for (int j = 0; j < 8; j++) acc[i][j] = 0.0f;

    for (int k0 = 0; k0 < DIN; k0 += 32) {
        __syncthreads();
#pragma unroll
        for (int i = tid; i < 64 * 32; i += 256) {
            int row = i >> 5, kk = i & 31;
            hs[kk * 68 + row] = h[(size_t)(r0 + row) * DIN + k0 + kk];
        }
#pragma unroll
        for (int i = tid; i < 32 * 128; i += 256) {
            int kk = i >> 7, d = i & 127;
            Ws[kk * 128 + d] = W[(size_t)(k0 + kk) * DOUT + d];
        }
        __syncthreads();

#pragma unroll 8
        for (int kk = 0; kk < 32; kk++) {
            float4 hv = *(const float4*)&hs[kk * 68 + ty * 4];
            float4 w0 = *(const float4*)&Ws[kk * 128 + tx * 8];
            float4 w1 = *(const float4*)&Ws[kk * 128 + tx * 8 + 4];
            float hr[4] = {hv.x, hv.y, hv.z, hv.w};
            float wr[8] = {w0.x, w0.y, w0.z, w0.w, w1.x, w1.y, w1.z, w1.w};
#pragma unroll
            for (int i = 0; i < 4; i++)
#pragma unroll
                for (int j = 0; j < 8; j++) acc[i][j] += hr[i] * wr[j];
        }
    }

    // fused epilogue: row norm across the 16 tx lanes (same warp half), then
    // write tf32-rounded Wh and Whn.
#pragma unroll
    for (int i = 0; i < 4; i++) {
        float ss = 0.0f;
#pragma unroll
        for (int j = 0; j < 8; j++) ss += acc[i][j] * acc[i][j];
        ss += __shfl_xor_sync(0xffffffffu, ss, 1);
        ss += __shfl_xor_sync(0xffffffffu, ss, 2);
        ss += __shfl_xor_sync(0xffffffffu, ss, 4);
        ss += __shfl_xor_sync(0xffffffffu, ss, 8);
        float inv = 1.0f / fmaxf(sqrtf(ss), 1e-12f);

        float o[8], on[8];
#pragma unroll
        for (int j = 0; j < 8; j++) {
            o[j]  = to_tf32(acc[i][j]);
            on[j] = to_tf32(acc[i][j] * inv);
        }
        size_t base = (size_t)(r0 + ty * 4 + i) * DOUT + tx * 8;
        *(float4*)&g_Wh [base]     = make_float4(o[0], o[1], o[2], o[3]);
        *(float4*)&g_Wh [base + 4] = make_float4(o[4], o[5], o[6], o[7]);
        *(float4*)&g_Whn[base]     = make_float4(on[0], on[1], on[2], on[3]);
        *(float4*)&g_Whn[base + 4] = make_float4(on[4], on[5], on[6], on[7]);
    }
}

// ---------------------------------------------------------------------------
// Phase 2: fused masked-softmax attention on tf32 tensor cores.
//   s = Whn_q . Whn_m  (0 if global q-row < 75)
//   p = adj_eye ? exp(s) : 0 ;  out = elu( (sum_m p*Wh_m) / sum_m p )
// Block: 128 q x full D, key tiles of 128. 8 warps, warp tile 32x64.
// ---------------------------------------------------------------------------
__global__ __launch_bounds__(256, 1) void attn(const int* __restrict__ adj,
                                               float* __restrict__ out) {
    extern __shared__ float sm[];
    float* Qs = sm;                 // [128][132] Whn query tile
    float* Ks = sm + TM * ST;       // [128][132] Whn key tile  (reused as Ps)
    float* Vs = Ks + TN * ST;       // [128][132] Wh key tile
    float* dn = Vs + TN * ST;       // [128] denominators
    float* Ps = Ks;                 // P overlays K (K dead after S)

    const int b    = blockIdx.y;
    const int q0   = blockIdx.x * TM;
    const int tid  = threadIdx.x;
    const int w    = tid >> 5, lane = tid & 31;
    const int mw   = (w & 3) * 32;   // warp's q-row offset (S + PV + O)
    const int nw   = (w >> 2) * 64;  // warp's key offset (S) / d offset (PV)
    const int qr   = lane >> 2, qc = lane & 3;

    const float* WhnB = g_Whn + (size_t)b * N_ * DOUT;
    const float* WhB  = g_Wh  + (size_t)b * N_ * DOUT;
    const int*   adjB = adj   + (size_t)b * N_ * N_;

    // Q tile (values already tf32-rounded)
#pragma unroll
    for (int i = tid; i < TM * 32; i += 256) {
        int r = i >> 5, g = i & 31;
        *(float4*)&Qs[r * ST + g * 4] = *(const float4*)&WhnB[(size_t)(q0 + r) * DOUT + g * 4];
    }
    if (tid < TM) dn[tid] = 0.0f;

    float oacc[2][8][4];
#pragma unroll
    for (int mb = 0; mb < 2; mb++)
#pragma unroll
        for (int nb = 0; nb < 8; nb++)
#pragma unroll
            for (int c = 0; c < 4; c++) oacc[mb][nb][c] = 0.0f;
    float rsum[4] = {0.f, 0.f, 0.f, 0.f};   // [mb*2+rp] row-sum partials

    const bool zr0a = (q0 + mw + qr)      < ROWZ;   // mb=0, rp=0
    const bool zr0b = (q0 + mw + 8 + qr)  < ROWZ;   // mb=0, rp=1
    const bool zr1a = (q0 + mw + 16 + qr) < ROWZ;   // mb=1, rp=0
    const bool zr1b = (q0 + mw + 24 + qr) < ROWZ;   // mb=1, rp=1

    for (int m0 = 0; m0 < N_; m0 += TN) {
        __syncthreads();   // prior PV readers done; smem reusable
        // K, V tiles
#pragma unroll
        for (int i = tid; i < TN * 32; i += 256) {
            int r = i >> 5, g = i & 31;
            *(float4*)&Ks[r * ST + g * 4] = *(const float4*)&WhnB[(size_t)(m0 + r) * DOUT + g * 4];
            *(float4*)&Vs[r * ST + g * 4] = *(const float4*)&WhB [(size_t)(m0 + r) * DOUT + g * 4];
        }
        // adjacency prefetch, bit-packed: bit(mb)[rp*16 + nb*2 + c]
        unsigned msk[2] = {0u, 0u};
#pragma unroll
        for (int mb = 0; mb < 2; mb++)
#pragma unroll
            for (int rp = 0; rp < 2; rp++) {
                int row = q0 + mw + 16 * mb + 8 * rp + qr;
                const int* ap = adjB + (size_t)row * N_ + m0 + nw + 2 * qc;
#pragma unroll
                for (int nb = 0; nb < 8; nb++) {
                    int2 v = *(const int2*)(ap + nb * 8);
                    msk[mb] |= (unsigned)(v.x > 0) << (rp * 16 + nb * 2);
                    msk[mb] |= (unsigned)(v.y > 0) << (rp * 16 + nb * 2 + 1);
                }
            }
        __syncthreads();   // tiles visible

        // ---- S = Q . K^T  (warp: 32 q x 64 keys) ----
        float sacc[2][8][4];
#pragma unroll
        for (int mb = 0; mb < 2; mb++)
#pragma unroll
            for (int nb = 0; nb < 8; nb++)
#pragma unroll
                for (int c = 0; c < 4; c++) sacc[mb][nb][c] = 0.0f;

#pragma unroll 4
        for (int k0 = 0; k0 < DOUT; k0 += 8) {
            unsigned a[2][4];
#pragma unroll
            for (int mb = 0; mb < 2; mb++) {
                int base = (mw + 16 * mb + qr) * ST + k0 + qc;
                a[mb][0] = *(const unsigned*)&Qs[base];
                a[mb][1] = *(const unsigned*)&Qs[base + 8 * ST];
                a[mb][2] = *(const unsigned*)&Qs[base + 4];
                a[mb][3] = *(const unsigned*)&Qs[base + 8 * ST + 4];
            }
#pragma unroll
            for (int nb = 0; nb < 8; nb++) {
                int bbase = (nw + 8 * nb + qr) * ST + k0 + qc;
                unsigned bb[2];
                bb[0] = *(const unsigned*)&Ks[bbase];
                bb[1] = *(const unsigned*)&Ks[bbase + 4];
                mma_tf32(sacc[0][nb], a[0], bb);
                mma_tf32(sacc[1][nb], a[1], bb);
            }
        }
        __syncthreads();   // everyone done reading Ks before P overwrite

        // ---- mask + exp -> P (tf32-rounded), accumulate row sums ----
#pragma unroll
        for (int mb = 0; mb < 2; mb++) {
            const bool za = mb ? zr1a : zr0a;
            const bool zb = mb ? zr1b : zr0b;
#pragma unroll
            for (int nb = 0; nb < 8; nb++) {
                unsigned m = msk[mb] >> (nb * 2);
                float p0 = (m & 1u)        ? __expf(za ? 0.f : sacc[mb][nb][0]) : 0.f;
                float p1 = (m & 2u)        ? __expf(za ? 0.f : sacc[mb][nb][1]) : 0.f;
                float p2 = ((m >> 16) & 1u) ? __expf(zb ? 0.f : sacc[mb][nb][2]) : 0.f;
                float p3 = ((m >> 16) & 2u) ? __expf(zb ? 0.f : sacc[mb][nb][3]) : 0.f;
                p0 = to_tf32(p0); p1 = to_tf32(p1); p2 = to_tf32(p2); p3 = to_tf32(p3);
                rsum[mb * 2]     += p0 + p1;
                rsum[mb * 2 + 1] += p2 + p3;
                int col = nw + 8 * nb + 2 * qc;
                *(float2*)&Ps[(mw + 16 * mb + qr) * ST + col]     = make_float2(p0, p1);
                *(float2*)&Ps[(mw + 16 * mb + 8 + qr) * ST + col] = make_float2(p2, p3);
            }
        }
        __syncthreads();   // Ps complete

        // ---- O += P . V  (warp: 32 q x 64 d, contraction over 128 keys) ----
#pragma unroll 4
        for (int k0 = 0; k0 < TN; k0 += 8) {
            unsigned a[2][4];
#pragma unroll
            for (int mb = 0; mb < 2; mb++) {
                int base = (mw + 16 * mb + qr) * ST + k0 + qc;
                a[mb][0] = *(const unsigned*)&Ps[base];
                a[mb][1] = *(const unsigned*)&Ps[base + 8 * ST];
                a[mb][2] = *(const unsigned*)&Ps[base + 4];
                a[mb][3] = *(const unsigned*)&Ps[base + 8 * ST + 4];
            }
#pragma unroll
            for (int nb = 0; nb < 8; nb++) {
                int dcol = nw + 8 * nb + qr;
                unsigned bb[2];
                bb[0] = *(const unsigned*)&Vs[(k0 + qc) * ST + dcol];
                bb[1] = *(const unsigned*)&Vs[(k0 + 4 + qc) * ST + dcol];
                mma_tf32(oacc[0][nb], a[0], bb);
                mma_tf32(oacc[1][nb], a[1], bb);
            }
        }
    }

    // denominators: reduce over the 4 qc lanes, one atomicAdd per row slot
#pragma unroll
    for (int i = 0; i < 4; i++) {
        float v = rsum[i];
        v += __shfl_xor_sync(0xffffffffu, v, 1);
        v += __shfl_xor_sync(0xffffffffu, v, 2);
        if (qc == 0) atomicAdd(&dn[mw + 16 * (i >> 1) + 8 * (i & 1) + qr], v);
    }
    __syncthreads();

    // epilogue: divide, ELU, store
#pragma unroll
    for (int mb = 0; mb < 2; mb++) {
        float i0 = 1.0f / fmaxf(dn[mw + 16 * mb + qr],     1e-30f);
        float i1 = 1.0f / fmaxf(dn[mw + 16 * mb + 8 + qr], 1e-30f);
        int r0 = q0 + mw + 16 * mb + qr;
#pragma unroll
        for (int nb = 0; nb < 8; nb++) {
            int col = nw + 8 * nb + 2 * qc;
            float v0 = oacc[mb][nb][0] * i0, v1 = oacc[mb][nb][1] * i0;
            float v2 = oacc[mb][nb][2] * i1, v3 = oacc[mb][nb][3] * i1;
            v0 = (v0 > 0.f) ? v0 : expm1f(v0);
            v1 = (v1 > 0.f) ? v1 : expm1f(v1);
            v2 = (v2 > 0.f) ? v2 : expm1f(v2);
            v3 = (v3 > 0.f) ? v3 : expm1f(v3);
            *(float2*)&out[((size_t)b * N_ + r0)     * DOUT + col] = make_float2(v0, v1);
            *(float2*)&out[((size_t)b * N_ + r0 + 8) * DOUT + col] = make_float2(v2, v3);
        }
    }
}

// ---------------------------------------------------------------------------
// Launch
// ---------------------------------------------------------------------------
extern "C" void kernel_launch(void* const* d_in, const int* in_sizes, int n_in,
                              void* d_out, int out_size) {
    const float* h       = (const float*)d_in[0];   // [8,2048,256] f32
    // d_in[1] = adj (unused by the reference math)
    const int*   adj_eye = (const int*)d_in[2];     // [8,2048,2048] i32
    const float* W       = (const float*)d_in[3];   // [256,128] f32
    float* out = (float*)d_out;                     // [8,2048,128] f32

    const int smem_bytes = (3 * TM * ST + 128) * 4;   // 203,264 B
    cudaFuncSetAttribute(attn, cudaFuncAttributeMaxDynamicSharedMemorySize, smem_bytes);

    gemm_hW<<<(B_ * N_) / 64, 256>>>(h, W);
    attn<<<dim3(N_ / TM, B_), 256, smem_bytes>>>(adj_eye, out);
}

// round 4
// speedup vs baseline: 3.2131x; 1.0543x over previous
#include <cuda_runtime.h>
#include <math.h>

#define B_   8
#define N_   2048
#define DIN  256
#define DOUT 128
#define ROWZ 75        // rows [0,75) get attscore = 0
#define TT   64        // attn tile (queries and keys)
#define ST   132       // Q/K smem row stride (floats)
#define PST  68        // P smem row stride

// Scratch (device globals: allocation-free). g_Wh stored tf32-rounded.
__device__ float g_Wh [B_ * N_ * DOUT];   // 8 MB
__device__ float g_inv[B_ * N_];          // 64 KB, fp32 inverse row norms

__device__ __forceinline__ float to_tf32(float x) {
    unsigned u;
    asm("cvt.rna.tf32.f32 %0, %1;" : "=r"(u) : "f"(x));
    return __uint_as_float(u);
}

__device__ __forceinline__ void mma_tf32(float d[4], const unsigned a[4], const unsigned b[2]) {
    asm volatile(
        "mma.sync.aligned.m16n8k8.row.col.f32.tf32.tf32.f32 "
        "{%0,%1,%2,%3}, {%4,%5,%6,%7}, {%8,%9}, {%0,%1,%2,%3};\n"
        : "+f"(d[0]), "+f"(d[1]), "+f"(d[2]), "+f"(d[3])
        : "r"(a[0]), "r"(a[1]), "r"(a[2]), "r"(a[3]), "r"(b[0]), "r"(b[1]));
}

// ---------------------------------------------------------------------------
// Phase 1: Wh = h @ W on tf32 MMA, fused row-norm.
// Block: 128 rows x 128 cols, K=256 in 8 chunks. 8 warps, warp tile 32x64.
// Writes g_Wh (tf32-rounded) and g_inv = 1/max(||row||, 1e-12).
// ---------------------------------------------------------------------------
__global__ __launch_bounds__(256) void gemmW(const float* __restrict__ h,
                                             const float* __restrict__ W) {
    __shared__ float hs[128 * 36];   // [row][k], stride 36
    __shared__ float Ws[32 * ST];    // [k][d],  stride 132
    __shared__ float sq[128];

    const int r0  = blockIdx.x * 128;
    const int tid = threadIdx.x;
    const int w   = tid >> 5, lane = tid & 31;
    const int mqw = (w & 3) * 32, dw = (w >> 2) * 64;
    const int qr  = lane >> 2,  qc = lane & 3;

    if (tid < 128) sq[tid] = 0.0f;

    float acc[2][8][4];
#pragma unroll
    for (int mb = 0; mb < 2; mb++)
#pragma unroll
        for (int nb = 0; nb < 8; nb++)
#pragma unroll
            for (int c = 0; c < 4; c++) acc[mb][nb][c] = 0.0f;

    for (int kc = 0; kc < 8; kc++) {
        __syncthreads();
#pragma unroll
        for (int i = tid; i < 128 * 8; i += 256) {
            int r = i >> 3, g = (i & 7) * 4;
            float4 v = *(const float4*)&h[(size_t)(r0 + r) * DIN + kc * 32 + g];
            v.x = to_tf32(v.x); v.y = to_tf32(v.y); v.z = to_tf32(v.z); v.w = to_tf32(v.w);
            *(float4*)&hs[r * 36 + g] = v;
        }
#pragma unroll
        for (int i = tid; i < 32 * 32; i += 256) {
            int r = i >> 5, g = (i & 31) * 4;
            float4 v = *(const float4*)&W[(size_t)(kc * 32 + r) * DOUT + g];
            v.x = to_tf32(v.x); v.y = to_tf32(v.y); v.z = to_tf32(v.z); v.w = to_tf32(v.w);
            *(float4*)&Ws[r * ST + g] = v;
        }
        __syncthreads();

#pragma unroll
        for (int k0 = 0; k0 < 32; k0 += 8) {
            unsigned a[2][4];
#pragma unroll
            for (int mb = 0; mb < 2; mb++) {
                int base = (mqw + 16 * mb + qr) * 36 + k0 + qc;
                a[mb][0] = *(const unsigned*)&hs[base];
                a[mb][1] = *(const unsigned*)&hs[base + 8 * 36];
                a[mb][2] = *(const unsigned*)&hs[base + 4];
                a[mb][3] = *(const unsigned*)&hs[base + 8 * 36 + 4];
            }
#pragma unroll
            for (int nb = 0; nb < 8; nb++) {
                unsigned bb[2];
                bb[0] = *(const unsigned*)&Ws[(k0 + qc) * ST + dw + 8 * nb + qr];
                bb[1] = *(const unsigned*)&Ws[(k0 + 4 + qc) * ST + dw + 8 * nb + qr];
                mma_tf32(acc[0][nb], a[0], bb);
                mma_tf32(acc[1][nb], a[1], bb);
            }
        }
    }

    // round to tf32, accumulate row square-sums
#pragma unroll
    for (int mb = 0; mb < 2; mb++) {
        float s0 = 0.0f, s1 = 0.0f;
#pragma unroll
        for (int nb = 0; nb < 8; nb++) {
#pragma unroll
            for (int c = 0; c < 4; c++) acc[mb][nb][c] = to_tf32(acc[mb][nb][c]);
            s0 += acc[mb][nb][0] * acc[mb][nb][0] + acc[mb][nb][1] * acc[mb][nb][1];
            s1 += acc[mb][nb][2] * acc[mb][nb][2] + acc[mb][nb][3] * acc[mb][nb][3];
        }
        s0 += __shfl_xor_sync(0xffffffffu, s0, 1); s0 += __shfl_xor_sync(0xffffffffu, s0, 2);
        s1 += __shfl_xor_sync(0xffffffffu, s1, 1); s1 += __shfl_xor_sync(0xffffffffu, s1, 2);
        if (qc == 0) {
            atomicAdd(&sq[mqw + 16 * mb + qr],     s0);
            atomicAdd(&sq[mqw + 16 * mb + 8 + qr], s1);
        }
    }
    __syncthreads();

#pragma unroll
    for (int mb = 0; mb < 2; mb++)
#pragma unroll
        for (int nb = 0; nb < 8; nb++) {
            int col = dw + 8 * nb + 2 * qc;
            size_t ra = (size_t)(r0 + mqw + 16 * mb + qr) * DOUT + col;
            size_t rb = (size_t)(r0 + mqw + 16 * mb + 8 + qr) * DOUT + col;
            *(float2*)&g_Wh[ra] = make_float2(acc[mb][nb][0], acc[mb][nb][1]);
            *(float2*)&g_Wh[rb] = make_float2(acc[mb][nb][2], acc[mb][nb][3]);
        }
    if (tid < 128) g_inv[r0 + tid] = 1.0f / fmaxf(sqrtf(sq[tid]), 1e-12f);
}

// ---------------------------------------------------------------------------
// Phase 2: fused masked-softmax attention, tf32 MMA, shared K=V buffer.
//   s = (Wh_q . Wh_m) * inv_q * inv_m   (0 if q-row < 75)
//   p = adj_eye ? exp(s) : 0 ;  out = elu( (sum p*Wh_m) / sum p )
// Block: 64 q, key tiles of 64. 8 warps; S warp tile 16x32, PV 16q x 64d.
// ---------------------------------------------------------------------------
__global__ __launch_bounds__(256, 2) void attn(const int* __restrict__ adj,
                                               float* __restrict__ out) {
    extern __shared__ float sm[];
    float* Qs   = sm;                    // [64][132]  Wh query tile
    float* Ks   = Qs + TT * ST;          // [64][132]  Wh key tile (= V)
    float* Ps   = Ks + TT * ST;          // [64][68]
    float* invq = Ps + TT * PST;
    float* invk = invq + TT;
    float* dn   = invk + TT;

    const int b   = blockIdx.y;
    const int q0  = blockIdx.x * TT;
    const int tid = threadIdx.x;
    const int w   = tid >> 5, lane = tid & 31;
    const int mqw = (w & 3) * 16;     // warp q offset
    const int nkw = (w >> 2) * 32;    // warp key offset (S)
    const int dw  = (w >> 2) * 64;    // warp d offset (PV)
    const int qr  = lane >> 2, qc = lane & 3;

    const float* WhB  = g_Wh  + (size_t)b * N_ * DOUT;
    const int*   adjB = adj   + (size_t)b * N_ * N_;

#pragma unroll
    for (int i = tid; i < TT * 32; i += 256) {
        int r = i >> 5, g = (i & 31) * 4;
        *(float4*)&Qs[r * ST + g] = *(const float4*)&WhB[(size_t)(q0 + r) * DOUT + g];
    }
    if (tid < TT) { invq[tid] = g_inv[b * N_ + q0 + tid]; dn[tid] = 0.0f; }
    __syncthreads();

    const float ivq0 = invq[mqw + qr], ivq1 = invq[mqw + 8 + qr];
    const bool  zq0  = (q0 + mqw + qr) < ROWZ;
    const bool  zq1  = (q0 + mqw + 8 + qr) < ROWZ;

    float oacc[8][4];
#pragma unroll
    for (int nb = 0; nb < 8; nb++)
#pragma unroll
        for (int c = 0; c < 4; c++) oacc[nb][c] = 0.0f;
    float rsum0 = 0.0f, rsum1 = 0.0f;

    for (int m0 = 0; m0 < N_; m0 += TT) {
        __syncthreads();   // prior tile's PV readers done
#pragma unroll
        for (int i = tid; i < TT * 32; i += 256) {
            int r = i >> 5, g = (i & 31) * 4;
            *(float4*)&Ks[r * ST + g] = *(const float4*)&WhB[(size_t)(m0 + r) * DOUT + g];
        }
        if (tid < TT) invk[tid] = g_inv[b * N_ + m0 + tid];

        unsigned msk = 0;
#pragma unroll
        for (int rp = 0; rp < 2; rp++) {
            const int* ap = adjB + (size_t)(q0 + mqw + 8 * rp + qr) * N_ + m0 + nkw + 2 * qc;
#pragma unroll
            for (int nb = 0; nb < 4; nb++) {
                int2 v = *(const int2*)(ap + nb * 8);
                msk |= (unsigned)(v.x > 0) << (rp * 8 + nb * 2);
                msk |= (unsigned)(v.y > 0) << (rp * 8 + nb * 2 + 1);
            }
        }
        __syncthreads();   // K tile + invk visible

        // ---- S = Q . K^T  (warp: 16q x 32k) ----
        float sacc[4][4];
#pragma unroll
        for (int nb = 0; nb < 4; nb++)
#pragma unroll
            for (int c = 0; c < 4; c++) sacc[nb][c] = 0.0f;

#pragma unroll
        for (int k0 = 0; k0 < DOUT; k0 += 8) {
            unsigned a[4];
            int base = (mqw + qr) * ST + k0 + qc;
            a[0] = *(const unsigned*)&Qs[base];
            a[1] = *(const unsigned*)&Qs[base + 8 * ST];
            a[2] = *(const unsigned*)&Qs[base + 4];
            a[3] = *(const unsigned*)&Qs[base + 8 * ST + 4];
#pragma unroll
            for (int nb = 0; nb < 4; nb++) {
                int bbase = (nkw + 8 * nb + qr) * ST + k0 + qc;
                unsigned bb[2];
                bb[0] = *(const unsigned*)&Ks[bbase];
                bb[1] = *(const unsigned*)&Ks[bbase + 4];
                mma_tf32(sacc[nb], a, bb);
            }
        }

        // ---- scale + mask + exp -> P ----
#pragma unroll
        for (int nb = 0; nb < 4; nb++) {
            int cb = nkw + 8 * nb + 2 * qc;
            float k0i = invk[cb], k1i = invk[cb + 1];
            unsigned ml = msk >> (nb * 2);
            unsigned mh = msk >> (8 + nb * 2);
            float p0 = (ml & 1u) ? __expf(zq0 ? 0.f : sacc[nb][0] * ivq0 * k0i) : 0.f;
            float p1 = (ml & 2u) ? __expf(zq0 ? 0.f : sacc[nb][1] * ivq0 * k1i) : 0.f;
            float p2 = (mh & 1u) ? __expf(zq1 ? 0.f : sacc[nb][2] * ivq1 * k0i) : 0.f;
            float p3 = (mh & 2u) ? __expf(zq1 ? 0.f : sacc[nb][3] * ivq1 * k1i) : 0.f;
            p0 = to_tf32(p0); p1 = to_tf32(p1); p2 = to_tf32(p2); p3 = to_tf32(p3);
            rsum0 += p0 + p1;
            rsum1 += p2 + p3;
            *(float2*)&Ps[(mqw + qr) * PST + cb]     = make_float2(p0, p1);
            *(float2*)&Ps[(mqw + 8 + qr) * PST + cb] = make_float2(p2, p3);
        }
        __syncthreads();   // P complete

        // ---- O += P . V  (warp: 16q x 64d, V = Ks) ----
#pragma unroll
        for (int k0 = 0; k0 < TT; k0 += 8) {
            unsigned a[4];
            int base = (mqw + qr) * PST + k0 + qc;
            a[0] = *(const unsigned*)&Ps[base];
            a[1] = *(const unsigned*)&Ps[base + 8 * PST];
            a[2] = *(const unsigned*)&Ps[base + 4];
            a[3] = *(const unsigned*)&Ps[base + 8 * PST + 4];
#pragma unroll
            for (int nb = 0; nb < 8; nb++) {
                int dcol = dw + 8 * nb + qr;
                unsigned bb[2];
                bb[0] = *(const unsigned*)&Ks[(k0 + qc) * ST + dcol];
                bb[1] = *(const unsigned*)&Ks[(k0 + 4 + qc) * ST + dcol];
                mma_tf32(oacc[nb], a, bb);
            }
        }
    }

    // denominators
    {
        float v0 = rsum0, v1 = rsum1;
        v0 += __shfl_xor_sync(0xffffffffu, v0, 1); v0 += __shfl_xor_sync(0xffffffffu, v0, 2);
        v1 += __shfl_xor_sync(0xffffffffu, v1, 1); v1 += __shfl_xor_sync(0xffffffffu, v1, 2);
        if (qc == 0) {
            atomicAdd(&dn[mqw + qr],     v0);
            atomicAdd(&dn[mqw + 8 + qr], v1);
        }
    }
    __syncthreads();

    // epilogue: divide, ELU, store
    {
        float i0 = 1.0f / fmaxf(dn[mqw + qr],     1e-30f);
        float i1 = 1.0f / fmaxf(dn[mqw + 8 + qr], 1e-30f);
        int r0 = q0 + mqw + qr;
#pragma unroll
        for (int nb = 0; nb < 8; nb++) {
            int col = dw + 8 * nb + 2 * qc;
            float v0 = oacc[nb][0] * i0, v1 = oacc[nb][1] * i0;
            float v2 = oacc[nb][2] * i1, v3 = oacc[nb][3] * i1;
            v0 = (v0 > 0.f) ? v0 : expm1f(v0);
            v1 = (v1 > 0.f) ? v1 : expm1f(v1);
            v2 = (v2 > 0.f) ? v2 : expm1f(v2);
            v3 = (v3 > 0.f) ? v3 : expm1f(v3);
            *(float2*)&out[((size_t)b * N_ + r0)     * DOUT + col] = make_float2(v0, v1);
            *(float2*)&out[((size_t)b * N_ + r0 + 8) * DOUT + col] = make_float2(v2, v3);
        }
    }
}

// ---------------------------------------------------------------------------
// Launch
// ---------------------------------------------------------------------------
extern "C" void kernel_launch(void* const* d_in, const int* in_sizes, int n_in,
                              void* d_out, int out_size) {
    const float* h       = (const float*)d_in[0];   // [8,2048,256] f32
    // d_in[1] = adj (unused by the reference math)
    const int*   adj_eye = (const int*)d_in[2];     // [8,2048,2048] i32
    const float* W       = (const float*)d_in[3];   // [256,128] f32
    float* out = (float*)d_out;                     // [8,2048,128] f32

    const int smem_bytes = (2 * TT * ST + TT * PST + 3 * TT) * 4;   // 85,760 B
    cudaFuncSetAttribute(attn, cudaFuncAttributeMaxDynamicSharedMemorySize, smem_bytes);

    gemmW<<<(B_ * N_) / 128, 256>>>(h, W);
    attn<<<dim3(N_ / TT, B_), 256, smem_bytes>>>(adj_eye, out);
}

// round 7
// speedup vs baseline: 3.8519x; 1.1988x over previous
#include <cuda_runtime.h>
#include <math.h>

#define B_   8
#define N_   2048
#define DIN  256
#define DOUT 128
#define ROWZ 75        // rows [0,75) get attscore = 0
#define TM   128       // queries per block
#define TN   128       // keys per tile
#define ST   132       // smem row stride (floats)

// Scratch (device globals: allocation-free). g_Wh stored tf32-rounded.
__device__ float g_Wh [B_ * N_ * DOUT];   // 8 MB
__device__ float g_inv[B_ * N_];          // 64 KB fp32 inverse row norms

__device__ __forceinline__ float to_tf32(float x) {
    unsigned u;
    asm("cvt.rna.tf32.f32 %0, %1;" : "=r"(u) : "f"(x));
    return __uint_as_float(u);
}

__device__ __forceinline__ void mma_tf32(float d[4], const unsigned a[4], const unsigned b[2]) {
    asm volatile(
        "mma.sync.aligned.m16n8k8.row.col.f32.tf32.tf32.f32 "
        "{%0,%1,%2,%3}, {%4,%5,%6,%7}, {%8,%9}, {%0,%1,%2,%3};\n"
        : "+f"(d[0]), "+f"(d[1]), "+f"(d[2]), "+f"(d[3])
        : "r"(a[0]), "r"(a[1]), "r"(a[2]), "r"(a[3]), "r"(b[0]), "r"(b[1]));
}

// ---------------------------------------------------------------------------
// Phase 1: Wh = h @ W on tf32 MMA, fused row-norm.
// Block: 128 rows x 128 cols, K=256 in 8 chunks. 8 warps, warp tile 32x64.
// Writes g_Wh (tf32-rounded) and g_inv = 1/max(||row||, 1e-12).
// ---------------------------------------------------------------------------
__global__ __launch_bounds__(256) void gemmW(const float* __restrict__ h,
                                             const float* __restrict__ W) {
    __shared__ float hs[128 * 36];
    __shared__ float Ws[32 * ST];
    __shared__ float sq[128];

    const int r0  = blockIdx.x * 128;
    const int tid = threadIdx.x;
    const int w   = tid >> 5, lane = tid & 31;
    const int mqw = (w & 3) * 32, dw = (w >> 2) * 64;
    const int qr  = lane >> 2,  qc = lane & 3;

    if (tid < 128) sq[tid] = 0.0f;

    float acc[2][8][4];
#pragma unroll
    for (int mb = 0; mb < 2; mb++)
#pragma unroll
        for (int nb = 0; nb < 8; nb++)
#pragma unroll
            for (int c = 0; c < 4; c++) acc[mb][nb][c] = 0.0f;

    for (int kc = 0; kc < 8; kc++) {
        __syncthreads();
#pragma unroll
        for (int i = tid; i < 128 * 8; i += 256) {
            int r = i >> 3, g = (i & 7) * 4;
            float4 v = *(const float4*)&h[(size_t)(r0 + r) * DIN + kc * 32 + g];
            v.x = to_tf32(v.x); v.y = to_tf32(v.y); v.z = to_tf32(v.z); v.w = to_tf32(v.w);
            *(float4*)&hs[r * 36 + g] = v;
        }
#pragma unroll
        for (int i = tid; i < 32 * 32; i += 256) {
            int r = i >> 5, g = (i & 31) * 4;
            float4 v = *(const float4*)&W[(size_t)(kc * 32 + r) * DOUT + g];
            v.x = to_tf32(v.x); v.y = to_tf32(v.y); v.z = to_tf32(v.z); v.w = to_tf32(v.w);
            *(float4*)&Ws[r * ST + g] = v;
        }
        __syncthreads();

#pragma unroll
        for (int k0 = 0; k0 < 32; k0 += 8) {
            unsigned a[2][4];
#pragma unroll
            for (int mb = 0; mb < 2; mb++) {
                int base = (mqw + 16 * mb + qr) * 36 + k0 + qc;
                a[mb][0] = *(const unsigned*)&hs[base];
                a[mb][1] = *(const unsigned*)&hs[base + 8 * 36];
                a[mb][2] = *(const unsigned*)&hs[base + 4];
                a[mb][3] = *(const unsigned*)&hs[base + 8 * 36 + 4];
            }
#pragma unroll
            for (int nb = 0; nb < 8; nb++) {
                unsigned bb[2];
                bb[0] = *(const unsigned*)&Ws[(k0 + qc) * ST + dw + 8 * nb + qr];
                bb[1] = *(const unsigned*)&Ws[(k0 + 4 + qc) * ST + dw + 8 * nb + qr];
                mma_tf32(acc[0][nb], a[0], bb);
                mma_tf32(acc[1][nb], a[1], bb);
            }
        }
    }

#pragma unroll
    for (int mb = 0; mb < 2; mb++) {
        float s0 = 0.0f, s1 = 0.0f;
#pragma unroll
        for (int nb = 0; nb < 8; nb++) {
#pragma unroll
            for (int c = 0; c < 4; c++) acc[mb][nb][c] = to_tf32(acc[mb][nb][c]);
            s0 += acc[mb][nb][0] * acc[mb][nb][0] + acc[mb][nb][1] * acc[mb][nb][1];
            s1 += acc[mb][nb][2] * acc[mb][nb][2] + acc[mb][nb][3] * acc[mb][nb][3];
        }
        s0 += __shfl_xor_sync(0xffffffffu, s0, 1); s0 += __shfl_xor_sync(0xffffffffu, s0, 2);
        s1 += __shfl_xor_sync(0xffffffffu, s1, 1); s1 += __shfl_xor_sync(0xffffffffu, s1, 2);
        if (qc == 0) {
            atomicAdd(&sq[mqw + 16 * mb + qr],     s0);
            atomicAdd(&sq[mqw + 16 * mb + 8 + qr], s1);
        }
    }
    __syncthreads();

#pragma unroll
    for (int mb = 0; mb < 2; mb++)
#pragma unroll
        for (int nb = 0; nb < 8; nb++) {
            int col = dw + 8 * nb + 2 * qc;
            size_t ra = (size_t)(r0 + mqw + 16 * mb + qr) * DOUT + col;
            size_t rb = (size_t)(r0 + mqw + 16 * mb + 8 + qr) * DOUT + col;
            *(float2*)&g_Wh[ra] = make_float2(acc[mb][nb][0], acc[mb][nb][1]);
            *(float2*)&g_Wh[rb] = make_float2(acc[mb][nb][2], acc[mb][nb][3]);
        }
    if (tid < 128) g_inv[r0 + tid] = 1.0f / fmaxf(sqrtf(sq[tid]), 1e-12f);
}

// ---------------------------------------------------------------------------
// Phase 2: fused masked-softmax attention, tf32 MMA.
// 512 threads, TM=TN=128. Warps: 4 q-bands(32q) x 4 splits (32k S / 32d PV).
// ---------------------------------------------------------------------------
__global__ __launch_bounds__(512, 1) void attn(const int* __restrict__ adj,
                                               float* __restrict__ out) {
    extern __shared__ float sm[];
    float* Qs   = sm;                  // [128][132] Wh query tile
    float* Ks   = Qs + TM * ST;        // [128][132] Wh key tile (= V)
    float* Ps   = Ks + TN * ST;        // [128][132] P
    float* invq = Ps + TM * ST;        // [128]
    float* invk = invq + 128;          // [128]
    float* dn   = invk + 128;          // [128]

    const int b    = blockIdx.y;
    const int q0   = blockIdx.x * TM;
    const int tid  = threadIdx.x;
    const int w    = tid >> 5, lane = tid & 31;
    const int band = w & 3, split = w >> 2;
    const int mqw  = band * 32;        // warp q offset
    const int nkw  = split * 32;       // warp key offset (S)
    const int dw   = split * 32;       // warp d offset (PV)
    const int qr   = lane >> 2, qc = lane & 3;

    const float* WhB  = g_Wh + (size_t)b * N_ * DOUT;
    const int*   adjB = adj  + (size_t)b * N_ * N_;

    // prologue: Q tile + invq + dn
#pragma unroll
    for (int i = tid; i < TM * 32; i += 512) {
        int r = i >> 5, g = (i & 31) * 4;
        *(float4*)&Qs[r * ST + g] = *(const float4*)&WhB[(size_t)(q0 + r) * DOUT + g];
    }
    if (tid < 128) { invq[tid] = g_inv[b * N_ + q0 + tid]; dn[tid] = 0.0f; }
    __syncthreads();

    // per-thread row constants (rows: mqw + 16*mb + 8*rp + qr)
    float ivq[4]; bool zq[4];
#pragma unroll
    for (int rr = 0; rr < 4; rr++) {
        int row = mqw + 16 * (rr >> 1) + 8 * (rr & 1) + qr;
        ivq[rr] = invq[row];
        zq[rr]  = (q0 + row) < ROWZ;
    }
    // adj row pointers (advance by TN each tile)
    const int* ap[4];
#pragma unroll
    for (int rr = 0; rr < 4; rr++)
        ap[rr] = adjB + (size_t)(q0 + mqw + 16 * (rr >> 1) + 8 * (rr & 1) + qr) * N_ + nkw + 2 * qc;

    float oacc[2][4][4];
#pragma unroll
    for (int mb = 0; mb < 2; mb++)
#pragma unroll
        for (int nb = 0; nb < 4; nb++)
#pragma unroll
            for (int c = 0; c < 4; c++) oacc[mb][nb][c] = 0.0f;
    float rsum[4] = {0.f, 0.f, 0.f, 0.f};

    for (int m0 = 0; m0 < N_; m0 += TN) {
        __syncthreads();   // prior PV done reading Ks
        // K(=V) tile + invk
#pragma unroll
        for (int i = tid; i < TN * 32; i += 512) {
            int r = i >> 5, g = (i & 31) * 4;
            *(float4*)&Ks[r * ST + g] = *(const float4*)&WhB[(size_t)(m0 + r) * DOUT + g];
        }
        if (tid < 128) invk[tid] = g_inv[b * N_ + m0 + tid];

        // adjacency masks for this warp's S region: bit = rr*8 + nb*2 + c
        unsigned msk = 0;
#pragma unroll
        for (int rr = 0; rr < 4; rr++) {
#pragma unroll
            for (int nb = 0; nb < 4; nb++) {
                int2 v = *(const int2*)(ap[rr] + 8 * nb);
                msk |= (unsigned)(v.x > 0) << (rr * 8 + nb * 2);
                msk |= (unsigned)(v.y > 0) << (rr * 8 + nb * 2 + 1);
            }
            ap[rr] += TN;
        }
        __syncthreads();   // K + invk visible

        // ---- S = Q.K^T  (warp: 32q x 32k) ----
        float sacc[2][4][4];
#pragma unroll
        for (int mb = 0; mb < 2; mb++)
#pragma unroll
            for (int nb = 0; nb < 4; nb++)
#pragma unroll
                for (int c = 0; c < 4; c++) sacc[mb][nb][c] = 0.0f;

#pragma unroll
        for (int k0 = 0; k0 < DOUT; k0 += 8) {
            unsigned a[2][4];
#pragma unroll
            for (int mb = 0; mb < 2; mb++) {
                int base = (mqw + 16 * mb + qr) * ST + k0 + qc;
                a[mb][0] = *(const unsigned*)&Qs[base];
                a[mb][1] = *(const unsigned*)&Qs[base + 8 * ST];
                a[mb][2] = *(const unsigned*)&Qs[base + 4];
                a[mb][3] = *(const unsigned*)&Qs[base + 8 * ST + 4];
            }
#pragma unroll
            for (int nb = 0; nb < 4; nb++) {
                int bbase = (nkw + 8 * nb + qr) * ST + k0 + qc;
                unsigned bb[2];
                bb[0] = *(const unsigned*)&Ks[bbase];
                bb[1] = *(const unsigned*)&Ks[bbase + 4];
                mma_tf32(sacc[0][nb], a[0], bb);
                mma_tf32(sacc[1][nb], a[1], bb);
            }
        }

        // ---- scale + mask + exp -> P ----
#pragma unroll
        for (int mb = 0; mb < 2; mb++) {
#pragma unroll
            for (int nb = 0; nb < 4; nb++) {
                int cb = nkw + 8 * nb + 2 * qc;
                float k0i = invk[cb], k1i = invk[cb + 1];
                unsigned ml = msk >> ((mb * 2)     * 8 + nb * 2);
                unsigned mh = msk >> ((mb * 2 + 1) * 8 + nb * 2);
                float p0 = (ml & 1u) ? __expf(zq[mb*2]   ? 0.f : sacc[mb][nb][0] * ivq[mb*2]   * k0i) : 0.f;
                float p1 = (ml & 2u) ? __expf(zq[mb*2]   ? 0.f : sacc[mb][nb][1] * ivq[mb*2]   * k1i) : 0.f;
                float p2 = (mh & 1u) ? __expf(zq[mb*2+1] ? 0.f : sacc[mb][nb][2] * ivq[mb*2+1] * k0i) : 0.f;
                float p3 = (mh & 2u) ? __expf(zq[mb*2+1] ? 0.f : sacc[mb][nb][3] * ivq[mb*2+1] * k1i) : 0.f;
                p0 = to_tf32(p0); p1 = to_tf32(p1); p2 = to_tf32(p2); p3 = to_tf32(p3);
                rsum[mb * 2]     += p0 + p1;
                rsum[mb * 2 + 1] += p2 + p3;
                *(float2*)&Ps[(mqw + 16 * mb + qr) * ST + cb]     = make_float2(p0, p1);
                *(float2*)&Ps[(mqw + 16 * mb + 8 + qr) * ST + cb] = make_float2(p2, p3);
            }
        }
        __syncthreads();   // P complete

        // ---- O += P.V  (warp: 32q x 32d, contraction over 128 keys) ----
#pragma unroll
        for (int k0 = 0; k0 < TN; k0 += 8) {
            unsigned a[2][4];
#pragma unroll
            for (int mb = 0; mb < 2; mb++) {
                int base = (mqw + 16 * mb + qr) * ST + k0 + qc;
                a[mb][0] = *(const unsigned*)&Ps[base];
                a[mb][1] = *(const unsigned*)&Ps[base + 8 * ST];
                a[mb][2] = *(const unsigned*)&Ps[base + 4];
                a[mb][3] = *(const unsigned*)&Ps[base + 8 * ST + 4];
            }
#pragma unroll
            for (int nb = 0; nb < 4; nb++) {
                int dcol = dw + 8 * nb + qr;
                unsigned bb[2];
                bb[0] = *(const unsigned*)&Ks[(k0 + qc) * ST + dcol];
                bb[1] = *(const unsigned*)&Ks[(k0 + 4 + qc) * ST + dcol];
                mma_tf32(oacc[0][nb], a[0], bb);
                mma_tf32(oacc[1][nb], a[1], bb);
            }
        }
    }

    // denominators (two split-warps per row band add their halves)
#pragma unroll
    for (int rr = 0; rr < 4; rr++) {
        float v = rsum[rr];
        v += __shfl_xor_sync(0xffffffffu, v, 1);
        v += __shfl_xor_sync(0xffffffffu, v, 2);
        if (qc == 0) atomicAdd(&dn[mqw + 16 * (rr >> 1) + 8 * (rr & 1) + qr], v);
    }
    __syncthreads();

    // epilogue: divide, ELU, store (warp: 32q x 32d)
#pragma unroll
    for (int mb = 0; mb < 2; mb++) {
        float i0 = 1.0f / fmaxf(dn[mqw + 16 * mb + qr],     1e-30f);
        float i1 = 1.0f / fmaxf(dn[mqw + 16 * mb + 8 + qr], 1e-30f);
        int r0 = q0 + mqw + 16 * mb + qr;
#pragma unroll
        for (int nb = 0; nb < 4; nb++) {
            int col = dw + 8 * nb + 2 * qc;
            float v0 = oacc[mb][nb][0] * i0, v1 = oacc[mb][nb][1] * i0;
            float v2 = oacc[mb][nb][2] * i1, v3 = oacc[mb][nb][3] * i1;
            v0 = (v0 > 0.f) ? v0 : expm1f(v0);
            v1 = (v1 > 0.f) ? v1 : expm1f(v1);
            v2 = (v2 > 0.f) ? v2 : expm1f(v2);
            v3 = (v3 > 0.f) ? v3 : expm1f(v3);
            *(float2*)&out[((size_t)b * N_ + r0)     * DOUT + col] = make_float2(v0, v1);
            *(float2*)&out[((size_t)b * N_ + r0 + 8) * DOUT + col] = make_float2(v2, v3);
        }
    }
}

// ---------------------------------------------------------------------------
// Launch
// ---------------------------------------------------------------------------
extern "C" void kernel_launch(void* const* d_in, const int* in_sizes, int n_in,
                              void* d_out, int out_size) {
    const float* h       = (const float*)d_in[0];   // [8,2048,256] f32
    // d_in[1] = adj (unused by the reference math)
    const int*   adj_eye = (const int*)d_in[2];     // [8,2048,2048] i32
    const float* W       = (const float*)d_in[3];   // [256,128] f32
    float* out = (float*)d_out;                     // [8,2048,128] f32

    const int smem_bytes = (3 * TM * ST + 3 * 128) * 4;   // 204,288 B
    cudaFuncSetAttribute(attn, cudaFuncAttributeMaxDynamicSharedMemorySize, smem_bytes);

    gemmW<<<(B_ * N_) / 128, 256>>>(h, W);
    attn<<<dim3(N_ / TM, B_), 512, smem_bytes>>>(adj_eye, out);
}